// round 1
// baseline (speedup 1.0000x reference)
#include <cuda_runtime.h>
#include <math.h>

#define NQ   2197
#define CDIM 216
#define KEYD 512
#define HCNT 8
#define HD   64
#define NHD  (NQ*HD)        /* 140608 */
#define FXD  338
#define FX2  114244         /* 338*338 */
#define LD   42
#define X4TOT 38614472      /* 338^3 == 8*2197^2 */
#define OUT3 74088          /* 42^3 */

/* ---------------- static device scratch (no runtime allocation) ---------------- */
__device__ float g_q[NQ*KEYD];
__device__ float g_k[NQ*KEYD];
__device__ float g_Qn[HCNT*NQ*HD];
__device__ float g_Kn[HCNT*NQ*HD];
__device__ float g_stats[2*HCNT*2];          /* [tensor][head][mean,rstd] */
__device__ float g_scores[(long)HCNT*NQ*NQ]; /* scoresT[h][m][q]; att in-place */
__device__ float g_att[(long)X4TOT];         /* fallback att(t,m) dest */
__device__ float g_x4[(long)X4TOT];
__device__ float g_out1[(long)LD*FX2];
__device__ float g_out2[LD*LD*FXD];

/* ---------------- generic fp32 GEMM: C[m][n] = alpha * sum_k A[m][k]*B[n][k] ----- */
__global__ void gemm_tn(const float* __restrict__ A, const float* __restrict__ B,
                        float* __restrict__ C, int M, int N, int K,
                        long sA, long sB, long sC, float alpha)
{
    int bz = blockIdx.z;
    A += (long)bz * sA; B += (long)bz * sB; C += (long)bz * sC;
    __shared__ float As[16][65];
    __shared__ float Bs[16][65];
    int tid = threadIdx.x;
    int tx = tid & 15, ty = tid >> 4;
    int m0 = blockIdx.x * 64, n0 = blockIdx.y * 64;
    float acc[4][4] = {};
    for (int k0 = 0; k0 < K; k0 += 16) {
#pragma unroll
        for (int l = 0; l < 4; l++) {
            int e = tid + l * 256;
            int r = e >> 4, c = e & 15;
            int kk = k0 + c;
            int mm = m0 + r;
            As[c][r] = (mm < M && kk < K) ? A[(long)mm * K + kk] : 0.f;
            int nn = n0 + r;
            Bs[c][r] = (nn < N && kk < K) ? B[(long)nn * K + kk] : 0.f;
        }
        __syncthreads();
#pragma unroll
        for (int kk = 0; kk < 16; kk++) {
            float av[4], bv[4];
#pragma unroll
            for (int i = 0; i < 4; i++) av[i] = As[kk][ty*4+i];
#pragma unroll
            for (int j = 0; j < 4; j++) bv[j] = Bs[kk][tx*4+j];
#pragma unroll
            for (int i = 0; i < 4; i++)
#pragma unroll
                for (int j = 0; j < 4; j++)
                    acc[i][j] += av[i] * bv[j];
        }
        __syncthreads();
    }
#pragma unroll
    for (int i = 0; i < 4; i++) {
        int mm = m0 + ty*4 + i;
        if (mm >= M) continue;
#pragma unroll
        for (int j = 0; j < 4; j++) {
            int nn = n0 + tx*4 + j;
            if (nn < N) C[(long)mm * N + nn] = alpha * acc[i][j];
        }
    }
}

/* ---------------- BN stats: per head mean / rstd over (N,HD) -------------------- */
__global__ void bn_stats_k()
{
    int h = blockIdx.x;
    int which = blockIdx.y;                 /* 0=q, 1=k */
    const float* src = which ? g_k : g_q;
    double s = 0.0, sq = 0.0;
    for (int i = threadIdx.x; i < NHD; i += 256) {
        int n = i >> 6, d = i & 63;
        float v = src[n*KEYD + h*HD + d];
        s += v; sq += (double)v * v;
    }
    __shared__ double rs[256], rq[256];
    rs[threadIdx.x] = s; rq[threadIdx.x] = sq;
    __syncthreads();
    for (int o = 128; o > 0; o >>= 1) {
        if (threadIdx.x < o) { rs[threadIdx.x] += rs[threadIdx.x+o]; rq[threadIdx.x] += rq[threadIdx.x+o]; }
        __syncthreads();
    }
    if (threadIdx.x == 0) {
        double mean = rs[0] / (double)NHD;
        double var  = rq[0] / (double)NHD - mean*mean;
        g_stats[(which*HCNT + h)*2 + 0] = (float)mean;
        g_stats[(which*HCNT + h)*2 + 1] = (float)rsqrt(var + 1e-5);
    }
}

/* ---------------- BN apply + L2 norm -> (h, n, 64) layout ----------------------- */
__global__ void bn_apply_k(const float* __restrict__ gamma, const float* __restrict__ beta)
{
    int h = blockIdx.y, which = blockIdx.z;
    int n = blockIdx.x*4 + (threadIdx.x >> 6);
    int d = threadIdx.x & 63;
    const float* src = which ? g_k : g_q;
    float* dst = which ? g_Kn : g_Qn;
    float mean = g_stats[(which*HCNT+h)*2];
    float rstd = g_stats[(which*HCNT+h)*2+1];
    float g = gamma[h], b = beta[h];
    float x = 0.f;
    if (n < NQ) x = (src[n*KEYD + h*HD + d] - mean)*rstd*g + b;
    float sq = x * x;
#pragma unroll
    for (int o = 16; o > 0; o >>= 1) sq += __shfl_xor_sync(0xffffffff, sq, o);
    __shared__ float part[8];
    int w = threadIdx.x >> 5;
    if ((threadIdx.x & 31) == 0) part[w] = sq;
    __syncthreads();
    int grp = threadIdx.x >> 6;
    float tot = part[grp*2] + part[grp*2+1];
    float y = x / fmaxf(sqrtf(tot), 1e-12f);
    if (n < NQ) dst[((long)h*NQ + n)*HD + d] = y;
}

/* ---------------- sparsemax over contiguous q per (h,m) row (Michelot) ---------- */
__global__ void sparsemax_k()
{
    long base = (long)blockIdx.x * NQ;
    __shared__ float z[NQ];
    __shared__ float rs[256];
    __shared__ int   rc[256];
    float s = 0.f;
    for (int i = threadIdx.x; i < NQ; i += 256) { float v = g_scores[base+i]; z[i] = v; s += v; }
    rs[threadIdx.x] = s;
    __syncthreads();
    for (int o = 128; o > 0; o >>= 1) {
        if (threadIdx.x < o) rs[threadIdx.x] += rs[threadIdx.x+o];
        __syncthreads();
    }
    float tau = (rs[0] - 1.f) / (float)NQ;
    __syncthreads();
    int cprev = NQ;
    for (int it = 0; it < 128; it++) {
        float ls = 0.f; int lc = 0;
        for (int i = threadIdx.x; i < NQ; i += 256) {
            float v = z[i];
            if (v > tau) { ls += v; lc++; }
        }
        rs[threadIdx.x] = ls; rc[threadIdx.x] = lc;
        __syncthreads();
        for (int o = 128; o > 0; o >>= 1) {
            if (threadIdx.x < o) { rs[threadIdx.x] += rs[threadIdx.x+o]; rc[threadIdx.x] += rc[threadIdx.x+o]; }
            __syncthreads();
        }
        int c = rc[0];
        float ssum = rs[0];
        __syncthreads();            /* protect rs[0]/rc[0] before next overwrite */
        if (c == 0) break;          /* uniform across block */
        tau = (ssum - 1.f) / (float)c;
        if (c == cprev) break;      /* support stable -> converged */
        cprev = c;
    }
    for (int i = threadIdx.x; i < NQ; i += 256) g_scores[base+i] = fmaxf(z[i] - tau, 0.f);
}

/* ---------------- att transpose: (h,m,q) -> att flat (t=8q+h, m) ---------------- */
__global__ void att_transpose_k(float* __restrict__ dst)
{
    __shared__ float tile[32][33];
    int h = blockIdx.z;
    int m0 = blockIdx.x * 32, q0 = blockIdx.y * 32;
#pragma unroll
    for (int r = 0; r < 4; r++) {
        int m = m0 + threadIdx.y + r*8;
        int q = q0 + threadIdx.x;
        if (m < NQ && q < NQ)
            tile[threadIdx.y + r*8][threadIdx.x] = g_scores[((long)(h*NQ+m))*NQ + q];
    }
    __syncthreads();
#pragma unroll
    for (int r = 0; r < 4; r++) {
        int q = q0 + threadIdx.y + r*8;
        int m = m0 + threadIdx.x;
        if (m < NQ && q < NQ)
            dst[((long)(8*q+h))*NQ + m] = tile[threadIdx.x][threadIdx.y + r*8];
    }
}

/* ---------------- x4[a,b,c] gather from att (t,m) layout ------------------------ */
__global__ void x4_permute_k(const float* __restrict__ att)
{
    long idx = (long)blockIdx.x * 256 + threadIdx.x;
    if (idx >= (long)X4TOT) return;
    int a = (int)(idx / FX2);
    int r = (int)(idx - (long)a*FX2);
    int bb = r / FXD;
    int c  = r - bb*FXD;
    int h1 = a / 169, ar = a - h1*169, i1 = ar / 13, i4 = ar - i1*13;
    int h2 = bb / 169, br = bb - h2*169, i2 = br / 13, i5 = br - i2*13;
    int h3 = c / 169, cr = c - h3*169, i3 = cr / 13, i6 = cr - i3*13;
    int t = (h1*4 + h2*2 + h3)*NQ + i1*169 + i2*13 + i3;
    int m = i4*169 + i5*13 + i6;
    g_x4[idx] = att[(long)t*NQ + m];
}

/* ---------------- TCL mode-1: out1[i][col] = sum_a W1[i][a]*x4[a][col] ---------- */
__global__ void tcl1_k(const float* __restrict__ W1)
{
    extern __shared__ float sW[];               /* 42*338 floats */
    for (int i = threadIdx.x; i < LD*FXD; i += 256) sW[i] = W1[i];
    __syncthreads();
    int col = blockIdx.x*256 + threadIdx.x;
    bool valid = col < FX2;
    float acc[LD];
#pragma unroll
    for (int i = 0; i < LD; i++) acc[i] = 0.f;
    for (int a = 0; a < FXD; a++) {
        float x = valid ? g_x4[(long)a*FX2 + col] : 0.f;
#pragma unroll
        for (int i = 0; i < LD; i++) acc[i] += sW[i*FXD + a] * x;
    }
    if (valid) {
#pragma unroll
        for (int i = 0; i < LD; i++) g_out1[(long)i*FX2 + col] = acc[i];
    }
}

/* ---------------- TCL mode-2: out2[i][j][c] = sum_b W2[j][b]*out1[i][b][c] ------ */
__global__ void tcl2_k(const float* __restrict__ W2)
{
    extern __shared__ float sW[];
    for (int i = threadIdx.x; i < LD*FXD; i += 256) sW[i] = W2[i];
    __syncthreads();
    int i = blockIdx.y;
    int c = blockIdx.x*256 + threadIdx.x;
    bool valid = c < FXD;
    float acc[LD];
#pragma unroll
    for (int j = 0; j < LD; j++) acc[j] = 0.f;
    for (int b = 0; b < FXD; b++) {
        float x = valid ? g_out1[(long)i*FX2 + b*FXD + c] : 0.f;
#pragma unroll
        for (int j = 0; j < LD; j++) acc[j] += sW[j*FXD + b] * x;
    }
    if (valid) {
#pragma unroll
        for (int j = 0; j < LD; j++) g_out2[(i*LD + j)*FXD + c] = acc[j];
    }
}

/* ---------------- TCL mode-3 + tanh: out[i][j][k] ------------------------------- */
__global__ void tcl3_k(const float* __restrict__ W3, float* __restrict__ outp)
{
    extern __shared__ float sm[];               /* sW3[42*338] + srow[338] */
    float* sW = sm;
    float* srow = sm + LD*FXD;
    int ij = blockIdx.x;
    for (int t = threadIdx.x; t < LD*FXD; t += 256) sW[t] = W3[t];
    for (int t = threadIdx.x; t < FXD; t += 256) srow[t] = g_out2[(long)ij*FXD + t];
    __syncthreads();
    if (threadIdx.x < LD) {
        int k = threadIdx.x;
        float s = 0.f;
        for (int c = 0; c < FXD; c++) s += sW[k*FXD + c] * srow[c];
        outp[ij*LD + k] = tanhf(s);
    }
}

/* ================================ host side ==================================== */
extern "C" void kernel_launch(void* const* d_in, const int* in_sizes, int n_in,
                              void* d_out, int out_size)
{
    const float* patches = (const float*)d_in[0];
    const float* Wq    = (const float*)d_in[1];
    const float* Wk    = (const float*)d_in[2];
    const float* gamma = (const float*)d_in[3];
    const float* beta  = (const float*)d_in[4];
    const float* W1    = (const float*)d_in[5];
    const float* W2    = (const float*)d_in[6];
    const float* W3    = (const float*)d_in[7];
    float* outp = (float*)d_out;
    (void)in_sizes; (void)n_in;

    float *pq, *pk, *pQn, *pKn, *pS, *pAttFallback;
    cudaGetSymbolAddress((void**)&pq,  g_q);
    cudaGetSymbolAddress((void**)&pk,  g_k);
    cudaGetSymbolAddress((void**)&pQn, g_Qn);
    cudaGetSymbolAddress((void**)&pKn, g_Kn);
    cudaGetSymbolAddress((void**)&pS,  g_scores);
    cudaGetSymbolAddress((void**)&pAttFallback, g_att);

    float* tanh_dest = nullptr;
    float* att_dest  = nullptr;
    if (out_size >= OUT3 + X4TOT)      { tanh_dest = outp; att_dest = outp + OUT3; }
    else if (out_size == X4TOT)        { att_dest = outp; }
    else                               { tanh_dest = outp; att_dest = pAttFallback; }

    cudaFuncSetAttribute(tcl1_k, cudaFuncAttributeMaxDynamicSharedMemorySize, 57344);
    cudaFuncSetAttribute(tcl2_k, cudaFuncAttributeMaxDynamicSharedMemorySize, 57344);
    cudaFuncSetAttribute(tcl3_k, cudaFuncAttributeMaxDynamicSharedMemorySize, 59392);

    const float inv_sqrt_dim = 0.06804138174397717f;  /* 1/sqrt(216) */

    /* 1,2: q/k projections */
    {
        dim3 g((NQ + 63)/64, (KEYD + 63)/64, 1);
        gemm_tn<<<g, 256>>>(patches, Wq, pq, NQ, KEYD, CDIM, 0, 0, 0, 1.f);
        gemm_tn<<<g, 256>>>(patches, Wk, pk, NQ, KEYD, CDIM, 0, 0, 0, 1.f);
    }
    /* 3: BN stats */
    bn_stats_k<<<dim3(HCNT, 2), 256>>>();
    /* 4: BN apply + l2 norm */
    bn_apply_k<<<dim3((NQ + 3)/4, HCNT, 2), 256>>>(gamma, beta);
    /* 5: scoresT[h][m][q] = Kn[h][m] . Qn[h][q] / sqrt(216) */
    {
        dim3 g((NQ + 63)/64, (NQ + 63)/64, HCNT);
        gemm_tn<<<g, 256>>>(pKn, pQn, pS, NQ, NQ, HD,
                            (long)NQ*HD, (long)NQ*HD, (long)NQ*NQ, inv_sqrt_dim);
    }
    /* 6: sparsemax in place over q */
    sparsemax_k<<<HCNT*NQ, 256>>>();
    /* 7: att output in flat (t=8q+h, m) layout */
    att_transpose_k<<<dim3((NQ+31)/32, (NQ+31)/32, HCNT), dim3(32, 8)>>>(att_dest);

    if (tanh_dest) {
        /* 8: build x4 */
        x4_permute_k<<<(X4TOT + 255)/256, 256>>>(att_dest);
        /* 9-11: TCL contractions + tanh */
        tcl1_k<<<(FX2 + 255)/256, 256, LD*FXD*4>>>(W1);
        tcl2_k<<<dim3((FXD + 255)/256, LD), 256, LD*FXD*4>>>(W2);
        tcl3_k<<<LD*LD, 256, (LD*FXD + FXD)*4>>>(W3, tanh_dest);
    }
}

// round 2
// speedup vs baseline: 1.3995x; 1.3995x over previous
#include <cuda_runtime.h>
#include <math.h>

#define NQ   2197
#define CDIM 216
#define KEYD 512
#define HCNT 8
#define HD   64
#define NHD  (NQ*HD)        /* 140608 */
#define FXD  338
#define FX2  114244         /* 338*338 */
#define LD   42
#define X4TOT 38614472      /* 338^3 == 8*2197^2 */
#define OUT3 74088          /* 42^3 */

/* ---------------- static device scratch (no runtime allocation) ---------------- */
__device__ float g_q[NQ*KEYD];
__device__ float g_k[NQ*KEYD];
__device__ float g_Qn[HCNT*NQ*HD];
__device__ float g_Kn[HCNT*NQ*HD];
__device__ float g_stats[2*HCNT*2];
__device__ float g_scores[(long)HCNT*NQ*NQ]; /* scoresT[h][m][q] */
__device__ float g_tau[HCNT*NQ];
__device__ float g_att[(long)X4TOT];         /* fallback att(t,m) dest */
__device__ float g_out1[(long)LD*FX2];
__device__ float g_out2[LD*LD*FXD];

/* ---------------- generic fp32 GEMM (used for q/k projections) ----------------- */
__global__ void gemm_tn(const float* __restrict__ A, const float* __restrict__ B,
                        float* __restrict__ C, int M, int N, int K, float alpha)
{
    __shared__ float As[16][65];
    __shared__ float Bs[16][65];
    int tid = threadIdx.x;
    int tx = tid & 15, ty = tid >> 4;
    int m0 = blockIdx.x * 64, n0 = blockIdx.y * 64;
    float acc[4][4] = {};
    for (int k0 = 0; k0 < K; k0 += 16) {
#pragma unroll
        for (int l = 0; l < 4; l++) {
            int e = tid + l * 256;
            int r = e >> 4, c = e & 15;
            int kk = k0 + c;
            int mm = m0 + r;
            As[c][r] = (mm < M && kk < K) ? A[(long)mm * K + kk] : 0.f;
            int nn = n0 + r;
            Bs[c][r] = (nn < N && kk < K) ? B[(long)nn * K + kk] : 0.f;
        }
        __syncthreads();
#pragma unroll
        for (int kk = 0; kk < 16; kk++) {
            float av[4], bv[4];
#pragma unroll
            for (int i = 0; i < 4; i++) av[i] = As[kk][ty*4+i];
#pragma unroll
            for (int j = 0; j < 4; j++) bv[j] = Bs[kk][tx*4+j];
#pragma unroll
            for (int i = 0; i < 4; i++)
#pragma unroll
                for (int j = 0; j < 4; j++)
                    acc[i][j] += av[i] * bv[j];
        }
        __syncthreads();
    }
#pragma unroll
    for (int i = 0; i < 4; i++) {
        int mm = m0 + ty*4 + i;
        if (mm >= M) continue;
#pragma unroll
        for (int j = 0; j < 4; j++) {
            int nn = n0 + tx*4 + j;
            if (nn < N) C[(long)mm * N + nn] = alpha * acc[i][j];
        }
    }
}

/* ---------------- scores GEMM: 128x128 tile, K=64, 8x8 per thread -------------- */
__global__ void score_gemm_k(float alpha)
{
    int h = blockIdx.z;
    const float* __restrict__ A = g_Kn + (long)h * NQ * HD;   /* m rows */
    const float* __restrict__ B = g_Qn + (long)h * NQ * HD;   /* q rows */
    float* __restrict__ C = g_scores + (long)h * NQ * NQ;

    __shared__ float As[32][132];
    __shared__ float Bs[32][132];

    int tid = threadIdx.x;
    int tx = tid & 15, ty = tid >> 4;
    int m0 = blockIdx.x * 128, n0 = blockIdx.y * 128;
    float acc[8][8] = {};

#pragma unroll
    for (int k0 = 0; k0 < HD; k0 += 32) {
#pragma unroll
        for (int l = 0; l < 4; l++) {
            int f = tid + l * 256;         /* 0..1023 float4 slots */
            int row = f >> 3;              /* 0..127 */
            int kq  = f & 7;               /* float4 within 32-float k-chunk */
            int mm = m0 + row;
            float4 va = make_float4(0.f,0.f,0.f,0.f);
            if (mm < NQ) va = *(const float4*)&A[(long)mm * HD + k0 + kq*4];
            As[kq*4+0][row] = va.x; As[kq*4+1][row] = va.y;
            As[kq*4+2][row] = va.z; As[kq*4+3][row] = va.w;
            int nn = n0 + row;
            float4 vb = make_float4(0.f,0.f,0.f,0.f);
            if (nn < NQ) vb = *(const float4*)&B[(long)nn * HD + k0 + kq*4];
            Bs[kq*4+0][row] = vb.x; Bs[kq*4+1][row] = vb.y;
            Bs[kq*4+2][row] = vb.z; Bs[kq*4+3][row] = vb.w;
        }
        __syncthreads();
#pragma unroll
        for (int k = 0; k < 32; k++) {
            float av[8], bv[8];
#pragma unroll
            for (int i = 0; i < 8; i++) av[i] = As[k][ty + 16*i];
#pragma unroll
            for (int j = 0; j < 8; j++) bv[j] = Bs[k][tx + 16*j];
#pragma unroll
            for (int i = 0; i < 8; i++)
#pragma unroll
                for (int j = 0; j < 8; j++)
                    acc[i][j] += av[i] * bv[j];
        }
        __syncthreads();
    }
#pragma unroll
    for (int i = 0; i < 8; i++) {
        int mm = m0 + ty + 16*i;
        if (mm >= NQ) continue;
        long rb = (long)mm * NQ;
#pragma unroll
        for (int j = 0; j < 8; j++) {
            int nn = n0 + tx + 16*j;
            if (nn < NQ) C[rb + nn] = alpha * acc[i][j];
        }
    }
}

/* ---------------- BN stats ------------------------------------------------------ */
__global__ void bn_stats_k()
{
    int h = blockIdx.x;
    int which = blockIdx.y;
    const float* src = which ? g_k : g_q;
    double s = 0.0, sq = 0.0;
    for (int i = threadIdx.x; i < NHD; i += 256) {
        int n = i >> 6, d = i & 63;
        float v = src[n*KEYD + h*HD + d];
        s += v; sq += (double)v * v;
    }
    __shared__ double rs[256], rq[256];
    rs[threadIdx.x] = s; rq[threadIdx.x] = sq;
    __syncthreads();
    for (int o = 128; o > 0; o >>= 1) {
        if (threadIdx.x < o) { rs[threadIdx.x] += rs[threadIdx.x+o]; rq[threadIdx.x] += rq[threadIdx.x+o]; }
        __syncthreads();
    }
    if (threadIdx.x == 0) {
        double mean = rs[0] / (double)NHD;
        double var  = rq[0] / (double)NHD - mean*mean;
        g_stats[(which*HCNT + h)*2 + 0] = (float)mean;
        g_stats[(which*HCNT + h)*2 + 1] = (float)rsqrt(var + 1e-5);
    }
}

/* ---------------- BN apply + L2 norm -> (h, n, 64) ------------------------------ */
__global__ void bn_apply_k(const float* __restrict__ gamma, const float* __restrict__ beta)
{
    int h = blockIdx.y, which = blockIdx.z;
    int n = blockIdx.x*4 + (threadIdx.x >> 6);
    int d = threadIdx.x & 63;
    const float* src = which ? g_k : g_q;
    float* dst = which ? g_Kn : g_Qn;
    float mean = g_stats[(which*HCNT+h)*2];
    float rstd = g_stats[(which*HCNT+h)*2+1];
    float g = gamma[h], b = beta[h];
    float x = 0.f;
    if (n < NQ) x = (src[n*KEYD + h*HD + d] - mean)*rstd*g + b;
    float sq = x * x;
#pragma unroll
    for (int o = 16; o > 0; o >>= 1) sq += __shfl_xor_sync(0xffffffff, sq, o);
    __shared__ float part[8];
    int w = threadIdx.x >> 5;
    if ((threadIdx.x & 31) == 0) part[w] = sq;
    __syncthreads();
    int grp = threadIdx.x >> 6;
    float tot = part[grp*2] + part[grp*2+1];
    float y = x / fmaxf(sqrtf(tot), 1e-12f);
    if (n < NQ) dst[((long)h*NQ + n)*HD + d] = y;
}

/* ---------------- sparsemax tau (Michelot), z in registers ---------------------- */
__global__ void sparsemax_tau_k()
{
    long base = (long)blockIdx.x * NQ;
    int tid = threadIdx.x;
    float z[9];
#pragma unroll
    for (int j = 0; j < 9; j++) {
        int i = tid + j*256;
        z[j] = (i < NQ) ? g_scores[base + i] : -3.4e38f;
    }
    __shared__ float shs[8];
    __shared__ int   shc[8];
    int lane = tid & 31, w = tid >> 5;

    /* total sum */
    float s = 0.f;
#pragma unroll
    for (int j = 0; j < 9; j++) if (z[j] > -3.0e38f) s += z[j];
#pragma unroll
    for (int o = 16; o > 0; o >>= 1) s += __shfl_xor_sync(0xffffffff, s, o);
    if (lane == 0) shs[w] = s;
    __syncthreads();
    if (w == 0) {
        float v = (lane < 8) ? shs[lane] : 0.f;
#pragma unroll
        for (int o = 4; o > 0; o >>= 1) v += __shfl_xor_sync(0xffffffff, v, o);
        if (lane == 0) shs[0] = v;
    }
    __syncthreads();
    float tau = (shs[0] - 1.f) / (float)NQ;
    __syncthreads();

    int cprev = NQ;
    for (int it = 0; it < 64; it++) {
        float ls = 0.f; int lc = 0;
#pragma unroll
        for (int j = 0; j < 9; j++) {
            float v = z[j];
            if (v > tau) { ls += v; lc++; }
        }
#pragma unroll
        for (int o = 16; o > 0; o >>= 1) {
            ls += __shfl_xor_sync(0xffffffff, ls, o);
            lc += __shfl_xor_sync(0xffffffff, lc, o);
        }
        if (lane == 0) { shs[w] = ls; shc[w] = lc; }
        __syncthreads();
        if (w == 0) {
            float vs = (lane < 8) ? shs[lane] : 0.f;
            int   vc = (lane < 8) ? shc[lane] : 0;
#pragma unroll
            for (int o = 4; o > 0; o >>= 1) {
                vs += __shfl_xor_sync(0xffffffff, vs, o);
                vc += __shfl_xor_sync(0xffffffff, vc, o);
            }
            if (lane == 0) { shs[0] = vs; shc[0] = vc; }
        }
        __syncthreads();
        int c = shc[0];
        float ssum = shs[0];
        __syncthreads();
        if (c == 0) break;
        tau = (ssum - 1.f) / (float)c;
        if (c == cprev) break;
        cprev = c;
    }
    if (tid == 0) g_tau[blockIdx.x] = tau;
}

/* ---------------- transpose + relu(z - tau): (h,m,q) -> att (t=8q+h, m) --------- */
__global__ void att_transpose_k(float* __restrict__ dst)
{
    __shared__ float tile[32][33];
    __shared__ float stau[32];
    int h = blockIdx.z;
    int m0 = blockIdx.x * 32, q0 = blockIdx.y * 32;
    if (threadIdx.y == 0) {
        int m = m0 + threadIdx.x;
        stau[threadIdx.x] = (m < NQ) ? g_tau[h*NQ + m] : 0.f;
    }
    __syncthreads();
#pragma unroll
    for (int r = 0; r < 4; r++) {
        int mr = threadIdx.y + r*8;
        int m = m0 + mr;
        int q = q0 + threadIdx.x;
        if (m < NQ && q < NQ)
            tile[mr][threadIdx.x] =
                fmaxf(g_scores[((long)(h*NQ+m))*NQ + q] - stau[mr], 0.f);
    }
    __syncthreads();
#pragma unroll
    for (int r = 0; r < 4; r++) {
        int q = q0 + threadIdx.y + r*8;
        int m = m0 + threadIdx.x;
        if (m < NQ && q < NQ)
            dst[((long)(8*q+h))*NQ + m] = tile[threadIdx.x][threadIdx.y + r*8];
    }
}

/* ---------------- TCL mode-1 with fused x4 gather from att(t,m) ----------------- */
__global__ void tcl1_k(const float* __restrict__ W1, const float* __restrict__ att)
{
    extern __shared__ float sW[];               /* 42*338 floats */
    for (int i = threadIdx.x; i < LD*FXD; i += 256) sW[i] = W1[i];
    __syncthreads();
    int col = blockIdx.x*256 + threadIdx.x;
    bool valid = col < FX2;
    int colc = valid ? col : 0;
    int bb = colc / FXD;
    int c  = colc - bb*FXD;
    int h2 = bb / 169, br = bb - h2*169, i2 = br / 13, i5 = br - i2*13;
    int h3 = c / 169,  cr = c - h3*169,  i3 = cr / 13, i6 = cr - i3*13;
    int mPart = i5*13 + i6;
    int tLow  = (h2*2 + h3)*NQ + i2*13 + i3;

    float acc[LD];
#pragma unroll
    for (int i = 0; i < LD; i++) acc[i] = 0.f;

    int a = 0;
#pragma unroll 1
    for (int h1 = 0; h1 < 2; h1++) {
#pragma unroll 1
        for (int i1 = 0; i1 < 13; i1++) {
            long rowBase = ((long)(tLow + h1*4*NQ + i1*169)) * NQ + mPart;
#pragma unroll 1
            for (int i4 = 0; i4 < 13; i4++) {
                float x = valid ? att[rowBase + (long)i4*169] : 0.f;
                const float* w = sW + a;
#pragma unroll
                for (int i = 0; i < LD; i++) acc[i] += w[i*FXD] * x;
                a++;
            }
        }
    }
    if (valid) {
#pragma unroll
        for (int i = 0; i < LD; i++) g_out1[(long)i*FX2 + col] = acc[i];
    }
}

/* ---------------- TCL mode-2 ---------------------------------------------------- */
__global__ void tcl2_k(const float* __restrict__ W2)
{
    extern __shared__ float sW[];
    for (int i = threadIdx.x; i < LD*FXD; i += 256) sW[i] = W2[i];
    __syncthreads();
    int i = blockIdx.y;
    int c = blockIdx.x*256 + threadIdx.x;
    bool valid = c < FXD;
    float acc[LD];
#pragma unroll
    for (int j = 0; j < LD; j++) acc[j] = 0.f;
    for (int b = 0; b < FXD; b++) {
        float x = valid ? g_out1[(long)i*FX2 + b*FXD + c] : 0.f;
#pragma unroll
        for (int j = 0; j < LD; j++) acc[j] += sW[j*FXD + b] * x;
    }
    if (valid) {
#pragma unroll
        for (int j = 0; j < LD; j++) g_out2[(i*LD + j)*FXD + c] = acc[j];
    }
}

/* ---------------- TCL mode-3 + tanh --------------------------------------------- */
__global__ void tcl3_k(const float* __restrict__ W3, float* __restrict__ outp)
{
    extern __shared__ float sm[];
    float* sW = sm;
    float* srow = sm + LD*FXD;
    int ij = blockIdx.x;
    for (int t = threadIdx.x; t < LD*FXD; t += 256) sW[t] = W3[t];
    for (int t = threadIdx.x; t < FXD; t += 256) srow[t] = g_out2[(long)ij*FXD + t];
    __syncthreads();
    if (threadIdx.x < LD) {
        int k = threadIdx.x;
        float s = 0.f;
        for (int cc = 0; cc < FXD; cc++) s += sW[k*FXD + cc] * srow[cc];
        outp[ij*LD + k] = tanhf(s);
    }
}

/* ================================ host side ==================================== */
extern "C" void kernel_launch(void* const* d_in, const int* in_sizes, int n_in,
                              void* d_out, int out_size)
{
    const float* patches = (const float*)d_in[0];
    const float* Wq    = (const float*)d_in[1];
    const float* Wk    = (const float*)d_in[2];
    const float* gamma = (const float*)d_in[3];
    const float* beta  = (const float*)d_in[4];
    const float* W1    = (const float*)d_in[5];
    const float* W2    = (const float*)d_in[6];
    const float* W3    = (const float*)d_in[7];
    float* outp = (float*)d_out;
    (void)in_sizes; (void)n_in;

    float *pq, *pk, *pAttFallback;
    cudaGetSymbolAddress((void**)&pq,  g_q);
    cudaGetSymbolAddress((void**)&pk,  g_k);
    cudaGetSymbolAddress((void**)&pAttFallback, g_att);

    float* tanh_dest = nullptr;
    float* att_dest  = nullptr;
    if (out_size >= OUT3 + X4TOT)      { tanh_dest = outp; att_dest = outp + OUT3; }
    else if (out_size == X4TOT)        { att_dest = outp; }
    else                               { tanh_dest = outp; att_dest = pAttFallback; }

    cudaFuncSetAttribute(tcl1_k, cudaFuncAttributeMaxDynamicSharedMemorySize, 57344);
    cudaFuncSetAttribute(tcl2_k, cudaFuncAttributeMaxDynamicSharedMemorySize, 57344);
    cudaFuncSetAttribute(tcl3_k, cudaFuncAttributeMaxDynamicSharedMemorySize, 59392);

    const float inv_sqrt_dim = 0.06804138174397717f;  /* 1/sqrt(216) */

    /* 1,2: q/k projections */
    {
        dim3 g((NQ + 63)/64, (KEYD + 63)/64, 1);
        gemm_tn<<<g, 256>>>(patches, Wq, pq, NQ, KEYD, CDIM, 1.f);
        gemm_tn<<<g, 256>>>(patches, Wk, pk, NQ, KEYD, CDIM, 1.f);
    }
    /* 3: BN stats */
    bn_stats_k<<<dim3(HCNT, 2), 256>>>();
    /* 4: BN apply + l2 norm */
    bn_apply_k<<<dim3((NQ + 3)/4, HCNT, 2), 256>>>(gamma, beta);
    /* 5: scoresT[h][m][q] = Kn[h][m] . Qn[h][q] / sqrt(216) */
    score_gemm_k<<<dim3((NQ+127)/128, (NQ+127)/128, HCNT), 256>>>(inv_sqrt_dim);
    /* 6: sparsemax tau per (h,m) row */
    sparsemax_tau_k<<<HCNT*NQ, 256>>>();
    /* 7: relu(z - tau) + transpose into att (t=8q+h, m) layout */
    att_transpose_k<<<dim3((NQ+31)/32, (NQ+31)/32, HCNT), dim3(32, 8)>>>(att_dest);

    if (tanh_dest) {
        /* 8: TCL mode-1 with fused x4 gather */
        tcl1_k<<<(FX2 + 255)/256, 256, LD*FXD*4>>>(W1, att_dest);
        /* 9,10: remaining contractions + tanh */
        tcl2_k<<<dim3((FXD + 255)/256, LD), 256, LD*FXD*4>>>(W2);
        tcl3_k<<<LD*LD, 256, (LD*FXD + FXD)*4>>>(W3, tanh_dest);
    }
}